// round 6
// baseline (speedup 1.0000x reference)
#include <cuda_runtime.h>
#include <cuda_fp16.h>
#include <cstdint>

static constexpr int BM = 256;        // = M: weight read exactly once
static constexpr int BN = 112;        // 28672/112 = 256 CTAs -> 2 balanced waves
static constexpr int BK = 128;
static constexpr int THREADS = 512;

static constexpr int A_STRIDE = 144;  // 128 + 16 pad
static constexpr int W_STRIDE = 144;  // packed int8 rows, 128 + 16 pad
static constexpr int A_BYTES  = BM * A_STRIDE;          // 36864
static constexpr int W_BYTES  = BN * W_STRIDE;          // 16128
static constexpr int SM_HDR   = 1024;
static constexpr int SM_STAGE = A_BYTES + W_BYTES;      // 52992
static constexpr int SM_TOTAL = SM_HDR + 2 * SM_STAGE;  // 106988 -> 107008

// Static scratch: quantized activations + per-token scales.
__device__ __align__(16) int8_t g_qx[256 * 8192];
__device__ float g_ascale[256];

__device__ __forceinline__ uint32_t smem_u32(const void* p) {
    return (uint32_t)__cvta_generic_to_shared(p);
}
__device__ __forceinline__ uint32_t pack4(uint4 v) {
    uint32_t t0 = __byte_perm(v.x, v.y, 0x0040);
    uint32_t t1 = __byte_perm(v.z, v.w, 0x0040);
    return __byte_perm(t0, t1, 0x5410);
}

// ---------------------------------------------------------------------------
// dtype detection (verified in round 3)
// ---------------------------------------------------------------------------
__device__ __forceinline__ int classify16(const uint16_t* p, float lo, float hi) {
    int cbf = 0, cf16 = 0;
    #pragma unroll 8
    for (int i = 0; i < 128; i++) {
        uint32_t u = p[i];
        float vb = __uint_as_float(u << 16);
        float ab = fabsf(vb);
        if (ab >= lo && ab <= hi) cbf++;
        float vh = __half2float(__ushort_as_half((unsigned short)u));
        float ah = fabsf(vh);
        if (ah >= lo && ah <= hi) cf16++;
    }
    if (cbf  >= 96) return 2;
    if (cf16 >= 96) return 1;
    return 0;
}
__device__ __forceinline__ bool weight_is_i32(const void* w) {
    const int* wi = (const int*)w;
    bool all = true;
    #pragma unroll
    for (int j = 0; j < 8; j++) {
        int v = wi[j];
        all = all && (v >= -128 && v <= 127);
    }
    return all;
}

// ---------------------------------------------------------------------------
// Kernel 1: per-token int8 quantization (verified, unchanged)
// ---------------------------------------------------------------------------
template <int MODE>
__global__ void __launch_bounds__(256) quant_kernel(const void* __restrict__ xv,
                                                    int K) {
    if (classify16((const uint16_t*)xv, 0.05f, 30.0f) != MODE) return;

    const int m   = blockIdx.x;
    const int tid = threadIdx.x;

    float vals[32];
    float mx = 0.f;

    #pragma unroll
    for (int i = 0; i < 4; i++) {
        float f[8];
        if (MODE == 0) {
            const uint4* x4 = (const uint4*)((const float*)xv + (size_t)m * K);
            uint4 v0 = x4[(i * 256 + tid) * 2];
            uint4 v1 = x4[(i * 256 + tid) * 2 + 1];
            f[0] = __uint_as_float(v0.x); f[1] = __uint_as_float(v0.y);
            f[2] = __uint_as_float(v0.z); f[3] = __uint_as_float(v0.w);
            f[4] = __uint_as_float(v1.x); f[5] = __uint_as_float(v1.y);
            f[6] = __uint_as_float(v1.z); f[7] = __uint_as_float(v1.w);
        } else {
            const uint4* x4 = (const uint4*)((const uint16_t*)xv + (size_t)m * K);
            uint4 v = x4[i * 256 + tid];
            uint32_t w[4] = {v.x, v.y, v.z, v.w};
            #pragma unroll
            for (int j = 0; j < 4; j++) {
                uint32_t lo = w[j] & 0xFFFFu, hi = w[j] >> 16;
                if (MODE == 1) {
                    f[j * 2]     = __half2float(__ushort_as_half((unsigned short)lo));
                    f[j * 2 + 1] = __half2float(__ushort_as_half((unsigned short)hi));
                } else {
                    f[j * 2]     = __uint_as_float(lo << 16);
                    f[j * 2 + 1] = __uint_as_float(hi << 16);
                }
            }
        }
        #pragma unroll
        for (int j = 0; j < 8; j++) {
            vals[i * 8 + j] = f[j];
            mx = fmaxf(mx, fabsf(f[j]));
        }
    }

    __shared__ float red[32];
    #pragma unroll
    for (int o = 16; o > 0; o >>= 1)
        mx = fmaxf(mx, __shfl_xor_sync(0xffffffffu, mx, o));
    int warp = tid >> 5, lane = tid & 31;
    if (lane == 0) red[warp] = mx;
    __syncthreads();
    if (warp == 0) {
        float v = (lane < 8) ? red[lane] : 0.f;
        #pragma unroll
        for (int o = 4; o > 0; o >>= 1)
            v = fmaxf(v, __shfl_xor_sync(0xffffffffu, v, o));
        if (lane == 0) {
            float scale = fmaxf(v, 1e-5f) / 127.0f;
            red[0] = scale;
            g_ascale[m] = scale;
        }
    }
    __syncthreads();
    const float scale = red[0];

    int8_t* qr = g_qx + (size_t)m * K;
    #pragma unroll
    for (int i = 0; i < 4; i++) {
        uint32_t packed[2];
        int8_t* pb = reinterpret_cast<int8_t*>(packed);
        #pragma unroll
        for (int j = 0; j < 8; j++) {
            int q = __float2int_rn(__fdiv_rn(vals[i * 8 + j], scale));
            q = max(-127, min(127, q));
            pb[j] = (int8_t)q;
        }
        reinterpret_cast<uint2*>(qr)[i * 256 + tid] = make_uint2(packed[0], packed[1]);
    }
}

// ---------------------------------------------------------------------------
// Kernel 2: int8 GEMM [256,K] x [N,K]^T -> int32, mma.sync.m16n8k32.
// A: cp.async double-buffered. W(int32): LDG.128 -> PRMT pack -> STS.32
// (packed int8 in smem), pipelined one tile ahead. Fused dequant epilogue.
// ---------------------------------------------------------------------------
template <bool WI32>
__global__ void __launch_bounds__(THREADS, 1) gemm_kernel(
    const void* __restrict__ Wv,
    const float* __restrict__ scale_channel,
    const void* __restrict__ p_bias,
    float* __restrict__ out,
    int N, int K)
{
    if (weight_is_i32(Wv) != WI32) return;

    extern __shared__ char smem[];
    const int tid  = threadIdx.x;
    const int warp = tid >> 5;
    const int lane = tid & 31;
    const int bn   = blockIdx.x;
    const int wm   = warp & 7;   // 8 warps along M: 8*32 = 256
    const int wn   = warp >> 3;  // 2 warps along N: 2*56 = 112

    const int*    gB32 = (const int*)Wv;
    const int8_t* gB8  = (const int8_t*)Wv;

    int acc[2][7][4];
    #pragma unroll
    for (int i = 0; i < 2; i++)
        #pragma unroll
        for (int j = 0; j < 7; j++)
            #pragma unroll
            for (int l = 0; l < 4; l++) acc[i][j][l] = 0;

    // W tile (int32 path): 112 rows x 32 chunks(16B) = 3584 = 7*512 tasks.
    uint32_t rw[7];
    auto ldgW = [&](int kt) {
        if (!WI32) return;
        const int k0 = kt * BK;
        #pragma unroll
        for (int i = 0; i < 7; i++) {
            int c   = tid + i * THREADS;
            int row = c >> 5;
            int ch  = c & 31;
            const int* src = gB32 + (size_t)(bn * BN + row) * K + k0 + ch * 4;
            rw[i] = pack4(*(const uint4*)src);
        }
    };
    auto stsW = [&](int st) {
        if (!WI32) return;
        char* wBase = smem + SM_HDR + st * SM_STAGE + A_BYTES;
        #pragma unroll
        for (int i = 0; i < 7; i++) {
            int c   = tid + i * THREADS;
            int row = c >> 5;
            int ch  = c & 31;
            *(uint32_t*)(wBase + row * W_STRIDE + ch * 4) = rw[i];
        }
    };
    // A tile via cp.async (+ W when already int8 in gmem)
    auto cpA = [&](int kt, int st) {
        char* aBase = smem + SM_HDR + st * SM_STAGE;
        const int k0 = kt * BK;
        #pragma unroll
        for (int i = 0; i < 4; i++) {
            int task = tid + i * THREADS;
            int row  = task >> 3;
            int ch   = (task & 7) * 16;
            uint32_t dst = smem_u32(aBase + row * A_STRIDE + ch);
            const int8_t* src = g_qx + (size_t)row * K + k0 + ch;
            asm volatile("cp.async.cg.shared.global [%0], [%1], 16;\n"
                         :: "r"(dst), "l"(src));
        }
        if (!WI32) {
            char* wBase = aBase + A_BYTES;
            for (int task = tid; task < BN * 8; task += THREADS) {
                int row = task >> 3;
                int ch  = (task & 7) * 16;
                uint32_t dst = smem_u32(wBase + row * W_STRIDE + ch);
                const int8_t* src = gB8 + (size_t)(bn * BN + row) * K + k0 + ch;
                asm volatile("cp.async.cg.shared.global [%0], [%1], 16;\n"
                             :: "r"(dst), "l"(src));
            }
        }
        asm volatile("cp.async.commit_group;\n");
    };

    const int NK = K / BK;   // 64

    // prologue
    ldgW(0);
    cpA(0, 0);
    cpA(1, 1);
    stsW(0);
    ldgW(1);

    for (int kt = 0; kt < NK; kt++) {
        if (kt + 1 < NK) asm volatile("cp.async.wait_group 1;\n");
        else             asm volatile("cp.async.wait_group 0;\n");
        __syncthreads();   // A(kt) + W(kt) visible

        const char* sA = smem + SM_HDR + (kt & 1) * SM_STAGE;
        const char* sW = sA + A_BYTES;

        #pragma unroll
        for (int kc = 0; kc < 4; kc++) {
            const int ofs = kc * 32 + (lane & 3) * 4;
            uint32_t a[2][4];
            #pragma unroll
            for (int mt = 0; mt < 2; mt++) {
                int row0 = wm * 32 + mt * 16 + (lane >> 2);
                a[mt][0] = *(const uint32_t*)(sA + row0 * A_STRIDE + ofs);
                a[mt][1] = *(const uint32_t*)(sA + (row0 + 8) * A_STRIDE + ofs);
                a[mt][2] = *(const uint32_t*)(sA + row0 * A_STRIDE + ofs + 16);
                a[mt][3] = *(const uint32_t*)(sA + (row0 + 8) * A_STRIDE + ofs + 16);
            }
            #pragma unroll
            for (int nt = 0; nt < 7; nt++) {
                int r = wn * 56 + nt * 8 + (lane >> 2);
                uint32_t b0 = *(const uint32_t*)(sW + r * W_STRIDE + ofs);
                uint32_t b1 = *(const uint32_t*)(sW + r * W_STRIDE + ofs + 16);
                #pragma unroll
                for (int mt = 0; mt < 2; mt++) {
                    asm volatile(
                        "mma.sync.aligned.m16n8k32.row.col.s32.s8.s8.s32 "
                        "{%0,%1,%2,%3}, {%4,%5,%6,%7}, {%8,%9}, {%0,%1,%2,%3};\n"
                        : "+r"(acc[mt][nt][0]), "+r"(acc[mt][nt][1]),
                          "+r"(acc[mt][nt][2]), "+r"(acc[mt][nt][3])
                        : "r"(a[mt][0]), "r"(a[mt][1]), "r"(a[mt][2]), "r"(a[mt][3]),
                          "r"(b0), "r"(b1));
                }
            }
        }

        __syncthreads();   // all reads of both stages done before refill
        if (kt + 2 < NK) cpA(kt + 2, kt & 1);
        if (kt + 1 < NK) stsW((kt + 1) & 1);
        if (kt + 2 < NK) ldgW(kt + 2);
    }

    // ---- stage per-channel scale + bias ----
    float* s_scale = (float*)(smem);
    float* s_bias  = (float*)(smem + 512);
    {
        int bmode = classify16((const uint16_t*)p_bias, 2e-4f, 0.5f);
        if (tid < BN) {
            int g = bn * BN + tid;
            s_scale[tid] = scale_channel[g];
            float b;
            if (bmode == 0)      b = ((const float*)p_bias)[g];
            else if (bmode == 1) b = __half2float(((const __half*)p_bias)[g]);
            else                 b = __uint_as_float(((uint32_t)((const uint16_t*)p_bias)[g]) << 16);
            s_bias[tid] = b;
        }
    }
    __syncthreads();

    // ---- fused dequant epilogue ----
    #pragma unroll
    for (int mt = 0; mt < 2; mt++) {
        int row0 = wm * 32 + mt * 16 + (lane >> 2);
        float s0 = g_ascale[row0];
        float s1 = g_ascale[row0 + 8];
        #pragma unroll
        for (int nt = 0; nt < 7; nt++) {
            int lc = wn * 56 + nt * 8 + (lane & 3) * 2;
            float sc0 = s_scale[lc], sc1 = s_scale[lc + 1];
            float b0  = s_bias[lc],  b1  = s_bias[lc + 1];
            int gcol = bn * BN + lc;
            float2 v0, v1;
            v0.x = (float)acc[mt][nt][0] * s0 * sc0 + b0;
            v0.y = (float)acc[mt][nt][1] * s0 * sc1 + b1;
            v1.x = (float)acc[mt][nt][2] * s1 * sc0 + b0;
            v1.y = (float)acc[mt][nt][3] * s1 * sc1 + b1;
            *reinterpret_cast<float2*>(out + (size_t)row0 * N + gcol)       = v0;
            *reinterpret_cast<float2*>(out + (size_t)(row0 + 8) * N + gcol) = v1;
        }
    }
}

// ---------------------------------------------------------------------------
extern "C" void kernel_launch(void* const* d_in, const int* in_sizes, int n_in,
                              void* d_out, int out_size) {
    const void*  x    = d_in[0];
    const void*  w    = d_in[1];
    const float* sc   = (const float*)d_in[2];
    const void*  bias = d_in[3];
    float* out = (float*)d_out;

    const int N = in_sizes[2];            // 28672
    const int K = in_sizes[1] / N;        // 8192
    const int M = in_sizes[0] / K;        // 256

    quant_kernel<0><<<M, 256>>>(x, K);
    quant_kernel<1><<<M, 256>>>(x, K);
    quant_kernel<2><<<M, 256>>>(x, K);

    cudaFuncSetAttribute(gemm_kernel<true >, cudaFuncAttributeMaxDynamicSharedMemorySize, SM_TOTAL);
    cudaFuncSetAttribute(gemm_kernel<false>, cudaFuncAttributeMaxDynamicSharedMemorySize, SM_TOTAL);

    dim3 grid(N / BN);                    // 256 CTAs
    gemm_kernel<true ><<<grid, THREADS, SM_TOTAL>>>(w, sc, bias, out, N, K);
    gemm_kernel<false><<<grid, THREADS, SM_TOTAL>>>(w, sc, bias, out, N, K);
}

// round 7
// speedup vs baseline: 1.0701x; 1.0701x over previous
#include <cuda_runtime.h>
#include <cuda_fp16.h>
#include <cstdint>

static constexpr int BM = 128;        // M split in 2 -> 512 CTAs, 2 resident/SM
static constexpr int BN = 112;
static constexpr int BK = 128;
static constexpr int THREADS = 256;

static constexpr int A_STRIDE = 144;  // 128 + 16 pad
static constexpr int W_STRIDE = 144;  // packed int8 rows, 128 + 16 pad
static constexpr int A_BYTES  = BM * A_STRIDE;          // 18432
static constexpr int W_BYTES  = BN * W_STRIDE;          // 16128
static constexpr int SM_HDR   = 1024;
static constexpr int SM_STAGE = A_BYTES + W_BYTES;      // 34560
static constexpr int SM_TOTAL = SM_HDR + 2 * SM_STAGE;  // 70144

// Static scratch: quantized activations + per-token scales.
__device__ __align__(16) int8_t g_qx[256 * 8192];
__device__ float g_ascale[256];

__device__ __forceinline__ uint32_t smem_u32(const void* p) {
    return (uint32_t)__cvta_generic_to_shared(p);
}
__device__ __forceinline__ uint32_t pack4(uint4 v) {
    uint32_t t0 = __byte_perm(v.x, v.y, 0x0040);
    uint32_t t1 = __byte_perm(v.z, v.w, 0x0040);
    return __byte_perm(t0, t1, 0x5410);
}

// ---------------------------------------------------------------------------
// dtype detection (verified in round 3)
// ---------------------------------------------------------------------------
__device__ __forceinline__ int classify16(const uint16_t* p, float lo, float hi) {
    int cbf = 0, cf16 = 0;
    #pragma unroll 8
    for (int i = 0; i < 128; i++) {
        uint32_t u = p[i];
        float vb = __uint_as_float(u << 16);
        float ab = fabsf(vb);
        if (ab >= lo && ab <= hi) cbf++;
        float vh = __half2float(__ushort_as_half((unsigned short)u));
        float ah = fabsf(vh);
        if (ah >= lo && ah <= hi) cf16++;
    }
    if (cbf  >= 96) return 2;
    if (cf16 >= 96) return 1;
    return 0;
}
__device__ __forceinline__ bool weight_is_i32(const void* w) {
    const int* wi = (const int*)w;
    bool all = true;
    #pragma unroll
    for (int j = 0; j < 8; j++) {
        int v = wi[j];
        all = all && (v >= -128 && v <= 127);
    }
    return all;
}

// ---------------------------------------------------------------------------
// Kernel 1: per-token int8 quantization (verified, unchanged)
// ---------------------------------------------------------------------------
template <int MODE>
__global__ void __launch_bounds__(256) quant_kernel(const void* __restrict__ xv,
                                                    int K) {
    if (classify16((const uint16_t*)xv, 0.05f, 30.0f) != MODE) return;

    const int m   = blockIdx.x;
    const int tid = threadIdx.x;

    float vals[32];
    float mx = 0.f;

    #pragma unroll
    for (int i = 0; i < 4; i++) {
        float f[8];
        if (MODE == 0) {
            const uint4* x4 = (const uint4*)((const float*)xv + (size_t)m * K);
            uint4 v0 = x4[(i * 256 + tid) * 2];
            uint4 v1 = x4[(i * 256 + tid) * 2 + 1];
            f[0] = __uint_as_float(v0.x); f[1] = __uint_as_float(v0.y);
            f[2] = __uint_as_float(v0.z); f[3] = __uint_as_float(v0.w);
            f[4] = __uint_as_float(v1.x); f[5] = __uint_as_float(v1.y);
            f[6] = __uint_as_float(v1.z); f[7] = __uint_as_float(v1.w);
        } else {
            const uint4* x4 = (const uint4*)((const uint16_t*)xv + (size_t)m * K);
            uint4 v = x4[i * 256 + tid];
            uint32_t w[4] = {v.x, v.y, v.z, v.w};
            #pragma unroll
            for (int j = 0; j < 4; j++) {
                uint32_t lo = w[j] & 0xFFFFu, hi = w[j] >> 16;
                if (MODE == 1) {
                    f[j * 2]     = __half2float(__ushort_as_half((unsigned short)lo));
                    f[j * 2 + 1] = __half2float(__ushort_as_half((unsigned short)hi));
                } else {
                    f[j * 2]     = __uint_as_float(lo << 16);
                    f[j * 2 + 1] = __uint_as_float(hi << 16);
                }
            }
        }
        #pragma unroll
        for (int j = 0; j < 8; j++) {
            vals[i * 8 + j] = f[j];
            mx = fmaxf(mx, fabsf(f[j]));
        }
    }

    __shared__ float red[32];
    #pragma unroll
    for (int o = 16; o > 0; o >>= 1)
        mx = fmaxf(mx, __shfl_xor_sync(0xffffffffu, mx, o));
    int warp = tid >> 5, lane = tid & 31;
    if (lane == 0) red[warp] = mx;
    __syncthreads();
    if (warp == 0) {
        float v = (lane < 8) ? red[lane] : 0.f;
        #pragma unroll
        for (int o = 4; o > 0; o >>= 1)
            v = fmaxf(v, __shfl_xor_sync(0xffffffffu, v, o));
        if (lane == 0) {
            float scale = fmaxf(v, 1e-5f) / 127.0f;
            red[0] = scale;
            g_ascale[m] = scale;
        }
    }
    __syncthreads();
    const float scale = red[0];

    int8_t* qr = g_qx + (size_t)m * K;
    #pragma unroll
    for (int i = 0; i < 4; i++) {
        uint32_t packed[2];
        int8_t* pb = reinterpret_cast<int8_t*>(packed);
        #pragma unroll
        for (int j = 0; j < 8; j++) {
            int q = __float2int_rn(__fdiv_rn(vals[i * 8 + j], scale));
            q = max(-127, min(127, q));
            pb[j] = (int8_t)q;
        }
        reinterpret_cast<uint2*>(qr)[i * 256 + tid] = make_uint2(packed[0], packed[1]);
    }
}

// ---------------------------------------------------------------------------
// Kernel 2: int8 GEMM [128,K] x [112,K]^T per CTA -> int32, m16n8k32.
// 256 threads, 2 CTAs/SM. A: cp.async double-buffer. W(int32): LDG.128 ->
// PRMT pack (14 regs) -> STS, pipelined one tile ahead. Fused dequant.
// ---------------------------------------------------------------------------
template <bool WI32>
__global__ void __launch_bounds__(THREADS, 2) gemm_kernel(
    const void* __restrict__ Wv,
    const float* __restrict__ scale_channel,
    const void* __restrict__ p_bias,
    float* __restrict__ out,
    int N, int K)
{
    if (weight_is_i32(Wv) != WI32) return;

    extern __shared__ char smem[];
    const int tid  = threadIdx.x;
    const int warp = tid >> 5;
    const int lane = tid & 31;
    const int bn   = blockIdx.x >> 1;   // N-stripe; same-bn pair adjacent -> L2 reuse
    const int bm   = blockIdx.x & 1;    // M half
    const int wm   = warp & 3;          // 4 warps along M: 4*32 = 128
    const int wn   = warp >> 2;         // 2 warps along N: 2*56 = 112

    const int*    gB32 = (const int*)Wv;
    const int8_t* gB8  = (const int8_t*)Wv;
    const int8_t* gA   = g_qx + (size_t)(bm * BM) * K;

    int acc[2][7][4];
    #pragma unroll
    for (int i = 0; i < 2; i++)
        #pragma unroll
        for (int j = 0; j < 7; j++)
            #pragma unroll
            for (int l = 0; l < 4; l++) acc[i][j][l] = 0;

    // W tile (int32 path): 112 rows x 32 chunks(16B) = 3584 = 14*256 tasks.
    uint32_t rw[14];
    auto ldgW = [&](int kt) {
        if (!WI32) return;
        const int k0 = kt * BK;
        #pragma unroll
        for (int i = 0; i < 14; i++) {
            int c   = tid + i * THREADS;
            int row = c >> 5;
            int ch  = c & 31;
            const int* src = gB32 + (size_t)(bn * BN + row) * K + k0 + ch * 4;
            rw[i] = pack4(*(const uint4*)src);
        }
    };
    auto stsW = [&](int st) {
        if (!WI32) return;
        char* wBase = smem + SM_HDR + st * SM_STAGE + A_BYTES;
        #pragma unroll
        for (int i = 0; i < 14; i++) {
            int c   = tid + i * THREADS;
            int row = c >> 5;
            int ch  = c & 31;
            *(uint32_t*)(wBase + row * W_STRIDE + ch * 4) = rw[i];
        }
    };
    // A tile via cp.async (+ W when already int8 in gmem)
    auto cpA = [&](int kt, int st) {
        char* aBase = smem + SM_HDR + st * SM_STAGE;
        const int k0 = kt * BK;
        #pragma unroll
        for (int i = 0; i < 4; i++) {
            int task = tid + i * THREADS;     // 0..1023
            int row  = task >> 3;             // 0..127
            int ch   = (task & 7) * 16;
            uint32_t dst = smem_u32(aBase + row * A_STRIDE + ch);
            const int8_t* src = gA + (size_t)row * K + k0 + ch;
            asm volatile("cp.async.cg.shared.global [%0], [%1], 16;\n"
                         :: "r"(dst), "l"(src));
        }
        if (!WI32) {
            char* wBase = aBase + A_BYTES;
            for (int task = tid; task < BN * 8; task += THREADS) {
                int row = task >> 3;
                int ch  = (task & 7) * 16;
                uint32_t dst = smem_u32(wBase + row * W_STRIDE + ch);
                const int8_t* src = gB8 + (size_t)(bn * BN + row) * K + k0 + ch;
                asm volatile("cp.async.cg.shared.global [%0], [%1], 16;\n"
                             :: "r"(dst), "l"(src));
            }
        }
        asm volatile("cp.async.commit_group;\n");
    };

    const int NK = K / BK;   // 64

    // prologue
    ldgW(0);
    cpA(0, 0);
    cpA(1, 1);
    stsW(0);
    ldgW(1);

    for (int kt = 0; kt < NK; kt++) {
        if (kt + 1 < NK) asm volatile("cp.async.wait_group 1;\n");
        else             asm volatile("cp.async.wait_group 0;\n");
        __syncthreads();   // stage(kt) fully ready (A via cp.async, W via STS)

        const char* sA = smem + SM_HDR + (kt & 1) * SM_STAGE;
        const char* sW = sA + A_BYTES;

        #pragma unroll
        for (int kc = 0; kc < 4; kc++) {
            const int ofs = kc * 32 + (lane & 3) * 4;
            uint32_t a[2][4];
            #pragma unroll
            for (int mt = 0; mt < 2; mt++) {
                int row0 = wm * 32 + mt * 16 + (lane >> 2);
                a[mt][0] = *(const uint32_t*)(sA + row0 * A_STRIDE + ofs);
                a[mt][1] = *(const uint32_t*)(sA + (row0 + 8) * A_STRIDE + ofs);
                a[mt][2] = *(const uint32_t*)(sA + row0 * A_STRIDE + ofs + 16);
                a[mt][3] = *(const uint32_t*)(sA + (row0 + 8) * A_STRIDE + ofs + 16);
            }
            #pragma unroll
            for (int nt = 0; nt < 7; nt++) {
                int r = wn * 56 + nt * 8 + (lane >> 2);
                uint32_t b0 = *(const uint32_t*)(sW + r * W_STRIDE + ofs);
                uint32_t b1 = *(const uint32_t*)(sW + r * W_STRIDE + ofs + 16);
                #pragma unroll
                for (int mt = 0; mt < 2; mt++) {
                    asm volatile(
                        "mma.sync.aligned.m16n8k32.row.col.s32.s8.s8.s32 "
                        "{%0,%1,%2,%3}, {%4,%5,%6,%7}, {%8,%9}, {%0,%1,%2,%3};\n"
                        : "+r"(acc[mt][nt][0]), "+r"(acc[mt][nt][1]),
                          "+r"(acc[mt][nt][2]), "+r"(acc[mt][nt][3])
                        : "r"(a[mt][0]), "r"(a[mt][1]), "r"(a[mt][2]), "r"(a[mt][3]),
                          "r"(b0), "r"(b1));
                }
            }
        }

        __syncthreads();   // all reads of both stages done before refill
        if (kt + 2 < NK) cpA(kt + 2, kt & 1);
        if (kt + 1 < NK) stsW((kt + 1) & 1);
        if (kt + 2 < NK) ldgW(kt + 2);
    }

    // ---- stage per-channel scale + bias ----
    float* s_scale = (float*)(smem);
    float* s_bias  = (float*)(smem + 512);
    {
        int bmode = classify16((const uint16_t*)p_bias, 2e-4f, 0.5f);
        if (tid < BN) {
            int g = bn * BN + tid;
            s_scale[tid] = scale_channel[g];
            float b;
            if (bmode == 0)      b = ((const float*)p_bias)[g];
            else if (bmode == 1) b = __half2float(((const __half*)p_bias)[g]);
            else                 b = __uint_as_float(((uint32_t)((const uint16_t*)p_bias)[g]) << 16);
            s_bias[tid] = b;
        }
    }
    __syncthreads();

    // ---- fused dequant epilogue ----
    #pragma unroll
    for (int mt = 0; mt < 2; mt++) {
        int row0 = bm * BM + wm * 32 + mt * 16 + (lane >> 2);
        float s0 = g_ascale[row0];
        float s1 = g_ascale[row0 + 8];
        #pragma unroll
        for (int nt = 0; nt < 7; nt++) {
            int lc = wn * 56 + nt * 8 + (lane & 3) * 2;
            float sc0 = s_scale[lc], sc1 = s_scale[lc + 1];
            float b0  = s_bias[lc],  b1  = s_bias[lc + 1];
            int gcol = bn * BN + lc;
            float2 v0, v1;
            v0.x = (float)acc[mt][nt][0] * s0 * sc0 + b0;
            v0.y = (float)acc[mt][nt][1] * s0 * sc1 + b1;
            v1.x = (float)acc[mt][nt][2] * s1 * sc0 + b0;
            v1.y = (float)acc[mt][nt][3] * s1 * sc1 + b1;
            *reinterpret_cast<float2*>(out + (size_t)row0 * N + gcol)       = v0;
            *reinterpret_cast<float2*>(out + (size_t)(row0 + 8) * N + gcol) = v1;
        }
    }
}

// ---------------------------------------------------------------------------
extern "C" void kernel_launch(void* const* d_in, const int* in_sizes, int n_in,
                              void* d_out, int out_size) {
    const void*  x    = d_in[0];
    const void*  w    = d_in[1];
    const float* sc   = (const float*)d_in[2];
    const void*  bias = d_in[3];
    float* out = (float*)d_out;

    const int N = in_sizes[2];            // 28672
    const int K = in_sizes[1] / N;        // 8192
    const int M = in_sizes[0] / K;        // 256

    quant_kernel<0><<<M, 256>>>(x, K);
    quant_kernel<1><<<M, 256>>>(x, K);
    quant_kernel<2><<<M, 256>>>(x, K);

    cudaFuncSetAttribute(gemm_kernel<true >, cudaFuncAttributeMaxDynamicSharedMemorySize, SM_TOTAL);
    cudaFuncSetAttribute(gemm_kernel<false>, cudaFuncAttributeMaxDynamicSharedMemorySize, SM_TOTAL);

    dim3 grid((N / BN) * (M / BM));       // 512 CTAs, 2 resident per SM
    gemm_kernel<true ><<<grid, THREADS, SM_TOTAL>>>(w, sc, bias, out, N, K);
    gemm_kernel<false><<<grid, THREADS, SM_TOTAL>>>(w, sc, bias, out, N, K);
}

// round 8
// speedup vs baseline: 1.0840x; 1.0129x over previous
#include <cuda_runtime.h>
#include <cuda_fp16.h>
#include <cstdint>

static constexpr int BM = 128;
static constexpr int BN = 112;
static constexpr int BK = 128;
static constexpr int THREADS = 256;
static constexpr int GRID = 296;      // 2 persistent CTAs per SM, one wave

static constexpr int A_STRIDE = 144;  // 128 + 16 pad
static constexpr int W_STRIDE = 144;
static constexpr int A_BYTES  = BM * A_STRIDE;          // 18432
static constexpr int W_BYTES  = BN * W_STRIDE;          // 16128
static constexpr int SM_HDR   = 1024;
static constexpr int SM_STAGE = A_BYTES + W_BYTES;      // 34560
static constexpr int SM_TOTAL = SM_HDR + 2 * SM_STAGE;  // 70144

// Static scratch: quantized activations + per-token scales.
__device__ __align__(16) int8_t g_qx[256 * 8192];
__device__ float g_ascale[256];

__device__ __forceinline__ uint32_t smem_u32(const void* p) {
    return (uint32_t)__cvta_generic_to_shared(p);
}
__device__ __forceinline__ uint32_t pack4(uint4 v) {
    uint32_t t0 = __byte_perm(v.x, v.y, 0x0040);
    uint32_t t1 = __byte_perm(v.z, v.w, 0x0040);
    return __byte_perm(t0, t1, 0x5410);
}

// ---------------------------------------------------------------------------
// dtype detection (verified in round 3)
// ---------------------------------------------------------------------------
__device__ __forceinline__ int classify16(const uint16_t* p, float lo, float hi) {
    int cbf = 0, cf16 = 0;
    #pragma unroll 8
    for (int i = 0; i < 128; i++) {
        uint32_t u = p[i];
        float vb = __uint_as_float(u << 16);
        float ab = fabsf(vb);
        if (ab >= lo && ab <= hi) cbf++;
        float vh = __half2float(__ushort_as_half((unsigned short)u));
        float ah = fabsf(vh);
        if (ah >= lo && ah <= hi) cf16++;
    }
    if (cbf  >= 96) return 2;
    if (cf16 >= 96) return 1;
    return 0;
}
__device__ __forceinline__ bool weight_is_i32(const void* w) {
    const int* wi = (const int*)w;
    bool all = true;
    #pragma unroll
    for (int j = 0; j < 8; j++) {
        int v = wi[j];
        all = all && (v >= -128 && v <= 127);
    }
    return all;
}

// ---------------------------------------------------------------------------
// Kernel 1: per-token int8 quantization (verified, unchanged)
// ---------------------------------------------------------------------------
template <int MODE>
__global__ void __launch_bounds__(256) quant_kernel(const void* __restrict__ xv,
                                                    int K) {
    if (classify16((const uint16_t*)xv, 0.05f, 30.0f) != MODE) return;

    const int m   = blockIdx.x;
    const int tid = threadIdx.x;

    float vals[32];
    float mx = 0.f;

    #pragma unroll
    for (int i = 0; i < 4; i++) {
        float f[8];
        if (MODE == 0) {
            const uint4* x4 = (const uint4*)((const float*)xv + (size_t)m * K);
            uint4 v0 = x4[(i * 256 + tid) * 2];
            uint4 v1 = x4[(i * 256 + tid) * 2 + 1];
            f[0] = __uint_as_float(v0.x); f[1] = __uint_as_float(v0.y);
            f[2] = __uint_as_float(v0.z); f[3] = __uint_as_float(v0.w);
            f[4] = __uint_as_float(v1.x); f[5] = __uint_as_float(v1.y);
            f[6] = __uint_as_float(v1.z); f[7] = __uint_as_float(v1.w);
        } else {
            const uint4* x4 = (const uint4*)((const uint16_t*)xv + (size_t)m * K);
            uint4 v = x4[i * 256 + tid];
            uint32_t w[4] = {v.x, v.y, v.z, v.w};
            #pragma unroll
            for (int j = 0; j < 4; j++) {
                uint32_t lo = w[j] & 0xFFFFu, hi = w[j] >> 16;
                if (MODE == 1) {
                    f[j * 2]     = __half2float(__ushort_as_half((unsigned short)lo));
                    f[j * 2 + 1] = __half2float(__ushort_as_half((unsigned short)hi));
                } else {
                    f[j * 2]     = __uint_as_float(lo << 16);
                    f[j * 2 + 1] = __uint_as_float(hi << 16);
                }
            }
        }
        #pragma unroll
        for (int j = 0; j < 8; j++) {
            vals[i * 8 + j] = f[j];
            mx = fmaxf(mx, fabsf(f[j]));
        }
    }

    __shared__ float red[32];
    #pragma unroll
    for (int o = 16; o > 0; o >>= 1)
        mx = fmaxf(mx, __shfl_xor_sync(0xffffffffu, mx, o));
    int warp = tid >> 5, lane = tid & 31;
    if (lane == 0) red[warp] = mx;
    __syncthreads();
    if (warp == 0) {
        float v = (lane < 8) ? red[lane] : 0.f;
        #pragma unroll
        for (int o = 4; o > 0; o >>= 1)
            v = fmaxf(v, __shfl_xor_sync(0xffffffffu, v, o));
        if (lane == 0) {
            float scale = fmaxf(v, 1e-5f) / 127.0f;
            red[0] = scale;
            g_ascale[m] = scale;
        }
    }
    __syncthreads();
    const float scale = red[0];

    int8_t* qr = g_qx + (size_t)m * K;
    #pragma unroll
    for (int i = 0; i < 4; i++) {
        uint32_t packed[2];
        int8_t* pb = reinterpret_cast<int8_t*>(packed);
        #pragma unroll
        for (int j = 0; j < 8; j++) {
            int q = __float2int_rn(__fdiv_rn(vals[i * 8 + j], scale));
            q = max(-127, min(127, q));
            pb[j] = (int8_t)q;
        }
        reinterpret_cast<uint2*>(qr)[i * 256 + tid] = make_uint2(packed[0], packed[1]);
    }
}

// ---------------------------------------------------------------------------
// Kernel 1b: initialize out[m][n] = bias[n] (float). Absorbs bias dtype hedge.
// ---------------------------------------------------------------------------
__global__ void __launch_bounds__(256) bias_init_kernel(
    const void* __restrict__ p_bias, float* __restrict__ out, int N, int total4)
{
    int bmode = classify16((const uint16_t*)p_bias, 2e-4f, 0.5f);
    int idx = blockIdx.x * 256 + threadIdx.x;
    if (idx >= total4) return;
    int n = (idx * 4) % N;
    float4 b;
    if (bmode == 0) {
        b = *(const float4*)((const float*)p_bias + n);
    } else if (bmode == 1) {
        const __half* bh = (const __half*)p_bias + n;
        b = make_float4(__half2float(bh[0]), __half2float(bh[1]),
                        __half2float(bh[2]), __half2float(bh[3]));
    } else {
        const uint16_t* bb = (const uint16_t*)p_bias + n;
        b = make_float4(__uint_as_float((uint32_t)bb[0] << 16),
                        __uint_as_float((uint32_t)bb[1] << 16),
                        __uint_as_float((uint32_t)bb[2] << 16),
                        __uint_as_float((uint32_t)bb[3] << 16));
    }
    *(float4*)(out + (size_t)idx * 4) = b;
}

// ---------------------------------------------------------------------------
// Kernel 2: persistent K-split int8 GEMM. 296 CTAs, each owns a contiguous
// range of (tile, k-tile) units; partial results combined via atomicAdd.
// unit u: tile = u/64 -> (bn = tile>>1, bm = tile&1), kt = u%64.
// ---------------------------------------------------------------------------
template <bool WI32>
__global__ void __launch_bounds__(THREADS, 2) gemm_kernel(
    const void* __restrict__ Wv,
    const float* __restrict__ scale_channel,
    float* __restrict__ out,
    int N, int K)
{
    if (weight_is_i32(Wv) != WI32) return;

    extern __shared__ char smem[];
    const int tid  = threadIdx.x;
    const int warp = tid >> 5;
    const int lane = tid & 31;
    const int wm   = warp & 3;          // 4 warps along M: 4*32 = 128
    const int wn   = warp >> 2;         // 2 warps along N: 2*56 = 112

    const int*    gB32 = (const int*)Wv;
    const int8_t* gB8  = (const int8_t*)Wv;

    const int NK     = K / BK;                    // 64
    const int tilesN = N / BN;                    // 256
    const int totalU = tilesN * 2 * NK;           // 32768
    const int per    = totalU / GRID;             // 110
    const int rem    = totalU % GRID;             // 208
    const int cta    = blockIdx.x;
    int u   = cta * per + min(cta, rem);
    const int uend = u + per + (cta < rem ? 1 : 0);

    float* s_scale = (float*)(smem);

    while (u < uend) {
        const int tile = u / NK;
        const int kt0  = u - tile * NK;
        const int kcnt = min(NK - kt0, uend - u);
        const int bn   = tile >> 1;
        const int bm   = tile & 1;
        const int8_t* gA = g_qx + (size_t)(bm * BM) * K;

        int acc[2][7][4];
        #pragma unroll
        for (int i = 0; i < 2; i++)
            #pragma unroll
            for (int j = 0; j < 7; j++)
                #pragma unroll
                for (int l = 0; l < 4; l++) acc[i][j][l] = 0;

        uint32_t rw[14];
        auto ldgW = [&](int j) {
            if (!WI32) return;
            const int k0 = (kt0 + j) * BK;
            #pragma unroll
            for (int i = 0; i < 14; i++) {
                int c   = tid + i * THREADS;
                int row = c >> 5;
                int ch  = c & 31;
                const int* src = gB32 + (size_t)(bn * BN + row) * K + k0 + ch * 4;
                rw[i] = pack4(*(const uint4*)src);
            }
        };
        auto stsW = [&](int st) {
            if (!WI32) return;
            char* wBase = smem + SM_HDR + st * SM_STAGE + A_BYTES;
            #pragma unroll
            for (int i = 0; i < 14; i++) {
                int c   = tid + i * THREADS;
                int row = c >> 5;
                int ch  = c & 31;
                *(uint32_t*)(wBase + row * W_STRIDE + ch * 4) = rw[i];
            }
        };
        auto cpA = [&](int j, int st) {
            char* aBase = smem + SM_HDR + st * SM_STAGE;
            const int k0 = (kt0 + j) * BK;
            #pragma unroll
            for (int i = 0; i < 4; i++) {
                int task = tid + i * THREADS;
                int row  = task >> 3;
                int ch   = (task & 7) * 16;
                uint32_t dst = smem_u32(aBase + row * A_STRIDE + ch);
                const int8_t* src = gA + (size_t)row * K + k0 + ch;
                asm volatile("cp.async.cg.shared.global [%0], [%1], 16;\n"
                             :: "r"(dst), "l"(src));
            }
            if (!WI32) {
                char* wBase = aBase + A_BYTES;
                for (int task = tid; task < BN * 8; task += THREADS) {
                    int row = task >> 3;
                    int ch  = (task & 7) * 16;
                    uint32_t dst = smem_u32(wBase + row * W_STRIDE + ch);
                    const int8_t* src = gB8 + (size_t)(bn * BN + row) * K + k0 + ch;
                    asm volatile("cp.async.cg.shared.global [%0], [%1], 16;\n"
                                 :: "r"(dst), "l"(src));
                }
            }
            asm volatile("cp.async.commit_group;\n");
        };

        // prologue
        ldgW(0);
        cpA(0, 0);
        if (kcnt > 1) cpA(1, 1);
        stsW(0);
        if (kcnt > 1) ldgW(1);

        for (int j = 0; j < kcnt; j++) {
            if (j + 1 < kcnt) asm volatile("cp.async.wait_group 1;\n");
            else              asm volatile("cp.async.wait_group 0;\n");
            __syncthreads();

            const char* sA = smem + SM_HDR + (j & 1) * SM_STAGE;
            const char* sW = sA + A_BYTES;

            #pragma unroll
            for (int kc = 0; kc < 4; kc++) {
                const int ofs = kc * 32 + (lane & 3) * 4;
                uint32_t a[2][4];
                #pragma unroll
                for (int mt = 0; mt < 2; mt++) {
                    int row0 = wm * 32 + mt * 16 + (lane >> 2);
                    a[mt][0] = *(const uint32_t*)(sA + row0 * A_STRIDE + ofs);
                    a[mt][1] = *(const uint32_t*)(sA + (row0 + 8) * A_STRIDE + ofs);
                    a[mt][2] = *(const uint32_t*)(sA + row0 * A_STRIDE + ofs + 16);
                    a[mt][3] = *(const uint32_t*)(sA + (row0 + 8) * A_STRIDE + ofs + 16);
                }
                #pragma unroll
                for (int nt = 0; nt < 7; nt++) {
                    int r = wn * 56 + nt * 8 + (lane >> 2);
                    uint32_t b0 = *(const uint32_t*)(sW + r * W_STRIDE + ofs);
                    uint32_t b1 = *(const uint32_t*)(sW + r * W_STRIDE + ofs + 16);
                    #pragma unroll
                    for (int mt = 0; mt < 2; mt++) {
                        asm volatile(
                            "mma.sync.aligned.m16n8k32.row.col.s32.s8.s8.s32 "
                            "{%0,%1,%2,%3}, {%4,%5,%6,%7}, {%8,%9}, {%0,%1,%2,%3};\n"
                            : "+r"(acc[mt][nt][0]), "+r"(acc[mt][nt][1]),
                              "+r"(acc[mt][nt][2]), "+r"(acc[mt][nt][3])
                            : "r"(a[mt][0]), "r"(a[mt][1]), "r"(a[mt][2]), "r"(a[mt][3]),
                              "r"(b0), "r"(b1));
                    }
                }
            }

            __syncthreads();
            if (j + 2 < kcnt) cpA(j + 2, j & 1);
            if (j + 1 < kcnt) stsW((j + 1) & 1);
            if (j + 2 < kcnt) ldgW(j + 2);
        }

        // ---- stage per-channel scales, then atomic dequant epilogue ----
        if (tid < BN) s_scale[tid] = scale_channel[bn * BN + tid];
        __syncthreads();

        #pragma unroll
        for (int mt = 0; mt < 2; mt++) {
            int row0 = bm * BM + wm * 32 + mt * 16 + (lane >> 2);
            float s0 = g_ascale[row0];
            float s1 = g_ascale[row0 + 8];
            #pragma unroll
            for (int nt = 0; nt < 7; nt++) {
                int lc = wn * 56 + nt * 8 + (lane & 3) * 2;
                float sc0 = s_scale[lc], sc1 = s_scale[lc + 1];
                int gcol = bn * BN + lc;
                float* o0 = out + (size_t)row0 * N + gcol;
                float* o1 = out + (size_t)(row0 + 8) * N + gcol;
                atomicAdd(o0,     (float)acc[mt][nt][0] * s0 * sc0);
                atomicAdd(o0 + 1, (float)acc[mt][nt][1] * s0 * sc1);
                atomicAdd(o1,     (float)acc[mt][nt][2] * s1 * sc0);
                atomicAdd(o1 + 1, (float)acc[mt][nt][3] * s1 * sc1);
            }
        }
        __syncthreads();   // s_scale reuse + smem stages safe for next segment

        u += kcnt;
    }
}

// ---------------------------------------------------------------------------
extern "C" void kernel_launch(void* const* d_in, const int* in_sizes, int n_in,
                              void* d_out, int out_size) {
    const void*  x    = d_in[0];
    const void*  w    = d_in[1];
    const float* sc   = (const float*)d_in[2];
    const void*  bias = d_in[3];
    float* out = (float*)d_out;

    const int N = in_sizes[2];            // 28672
    const int K = in_sizes[1] / N;        // 8192
    const int M = in_sizes[0] / K;        // 256

    quant_kernel<0><<<M, 256>>>(x, K);
    quant_kernel<1><<<M, 256>>>(x, K);
    quant_kernel<2><<<M, 256>>>(x, K);

    const int total4 = M * N / 4;
    bias_init_kernel<<<(total4 + 255) / 256, 256>>>(bias, out, N, total4);

    cudaFuncSetAttribute(gemm_kernel<true >, cudaFuncAttributeMaxDynamicSharedMemorySize, SM_TOTAL);
    cudaFuncSetAttribute(gemm_kernel<false>, cudaFuncAttributeMaxDynamicSharedMemorySize, SM_TOTAL);

    gemm_kernel<true ><<<GRID, THREADS, SM_TOTAL>>>(w, sc, out, N, K);
    gemm_kernel<false><<<GRID, THREADS, SM_TOTAL>>>(w, sc, out, N, K);
}

// round 9
// speedup vs baseline: 1.1803x; 1.0889x over previous
#include <cuda_runtime.h>
#include <cuda_fp16.h>
#include <cstdint>

static constexpr int BM = 128;
static constexpr int BN = 112;
static constexpr int BK = 128;
static constexpr int THREADS = 256;
static constexpr int GRID = 296;      // 2 persistent CTAs per SM, one wave

static constexpr int A_STRIDE = 144;  // 128 + 16 pad (36 banks -> ldmatrix conflict-free)
static constexpr int W_STRIDE = 144;
static constexpr int A_BYTES  = BM * A_STRIDE;          // 18432
static constexpr int W_BYTES  = BN * W_STRIDE;          // 16128
static constexpr int SM_HDR   = 1024;
static constexpr int SM_STAGE = A_BYTES + W_BYTES;      // 34560
static constexpr int SM_TOTAL = SM_HDR + 2 * SM_STAGE;  // 70144

// Static scratch: quantized activations + per-token scales + dtype flags.
__device__ __align__(16) int8_t g_qx[256 * 8192];
__device__ float g_ascale[256];
__device__ int g_xmode, g_bmode, g_wi32;

__device__ __forceinline__ uint32_t smem_u32(const void* p) {
    return (uint32_t)__cvta_generic_to_shared(p);
}
__device__ __forceinline__ uint32_t pack4(uint4 v) {
    uint32_t t0 = __byte_perm(v.x, v.y, 0x0040);
    uint32_t t1 = __byte_perm(v.z, v.w, 0x0040);
    return __byte_perm(t0, t1, 0x5410);
}
__device__ __forceinline__ void ldsm4(uint32_t* r, uint32_t a) {
    asm volatile("ldmatrix.sync.aligned.m8n8.x4.shared.b16 {%0,%1,%2,%3}, [%4];"
                 : "=r"(r[0]), "=r"(r[1]), "=r"(r[2]), "=r"(r[3]) : "r"(a));
}
__device__ __forceinline__ void ldsm2(uint32_t* r, uint32_t a) {
    asm volatile("ldmatrix.sync.aligned.m8n8.x2.shared.b16 {%0,%1}, [%2];"
                 : "=r"(r[0]), "=r"(r[1]) : "r"(a));
}

// ---------------------------------------------------------------------------
// dtype classification (logic verified in rounds 3-8); now run ONCE.
// ---------------------------------------------------------------------------
__device__ __forceinline__ int classify16(const uint16_t* p, float lo, float hi) {
    int cbf = 0, cf16 = 0;
    for (int i = 0; i < 128; i++) {
        uint32_t u = p[i];
        float vb = __uint_as_float(u << 16);
        float ab = fabsf(vb);
        if (ab >= lo && ab <= hi) cbf++;
        float vh = __half2float(__ushort_as_half((unsigned short)u));
        float ah = fabsf(vh);
        if (ah >= lo && ah <= hi) cf16++;
    }
    if (cbf  >= 96) return 2;
    if (cf16 >= 96) return 1;
    return 0;
}

__global__ void detect_kernel(const void* x, const void* bias, const void* w) {
    if (threadIdx.x == 0) {
        g_xmode = classify16((const uint16_t*)x, 0.05f, 30.0f);
        g_bmode = classify16((const uint16_t*)bias, 2e-4f, 0.5f);
        const int* wi = (const int*)w;
        bool all = true;
        #pragma unroll
        for (int j = 0; j < 8; j++) {
            int v = wi[j];
            all = all && (v >= -128 && v <= 127);
        }
        g_wi32 = all ? 1 : 0;
    }
}

// ---------------------------------------------------------------------------
// Kernel 1: per-token int8 quantization (verified; classify via flag)
// ---------------------------------------------------------------------------
template <int MODE>
__global__ void __launch_bounds__(256) quant_kernel(const void* __restrict__ xv,
                                                    int K) {
    if (g_xmode != MODE) return;

    const int m   = blockIdx.x;
    const int tid = threadIdx.x;

    float vals[32];
    float mx = 0.f;

    #pragma unroll
    for (int i = 0; i < 4; i++) {
        float f[8];
        if (MODE == 0) {
            const uint4* x4 = (const uint4*)((const float*)xv + (size_t)m * K);
            uint4 v0 = x4[(i * 256 + tid) * 2];
            uint4 v1 = x4[(i * 256 + tid) * 2 + 1];
            f[0] = __uint_as_float(v0.x); f[1] = __uint_as_float(v0.y);
            f[2] = __uint_as_float(v0.z); f[3] = __uint_as_float(v0.w);
            f[4] = __uint_as_float(v1.x); f[5] = __uint_as_float(v1.y);
            f[6] = __uint_as_float(v1.z); f[7] = __uint_as_float(v1.w);
        } else {
            const uint4* x4 = (const uint4*)((const uint16_t*)xv + (size_t)m * K);
            uint4 v = x4[i * 256 + tid];
            uint32_t w[4] = {v.x, v.y, v.z, v.w};
            #pragma unroll
            for (int j = 0; j < 4; j++) {
                uint32_t lo = w[j] & 0xFFFFu, hi = w[j] >> 16;
                if (MODE == 1) {
                    f[j * 2]     = __half2float(__ushort_as_half((unsigned short)lo));
                    f[j * 2 + 1] = __half2float(__ushort_as_half((unsigned short)hi));
                } else {
                    f[j * 2]     = __uint_as_float(lo << 16);
                    f[j * 2 + 1] = __uint_as_float(hi << 16);
                }
            }
        }
        #pragma unroll
        for (int j = 0; j < 8; j++) {
            vals[i * 8 + j] = f[j];
            mx = fmaxf(mx, fabsf(f[j]));
        }
    }

    __shared__ float red[32];
    #pragma unroll
    for (int o = 16; o > 0; o >>= 1)
        mx = fmaxf(mx, __shfl_xor_sync(0xffffffffu, mx, o));
    int warp = tid >> 5, lane = tid & 31;
    if (lane == 0) red[warp] = mx;
    __syncthreads();
    if (warp == 0) {
        float v = (lane < 8) ? red[lane] : 0.f;
        #pragma unroll
        for (int o = 4; o > 0; o >>= 1)
            v = fmaxf(v, __shfl_xor_sync(0xffffffffu, v, o));
        if (lane == 0) {
            float scale = fmaxf(v, 1e-5f) / 127.0f;
            red[0] = scale;
            g_ascale[m] = scale;
        }
    }
    __syncthreads();
    const float scale = red[0];

    int8_t* qr = g_qx + (size_t)m * K;
    #pragma unroll
    for (int i = 0; i < 4; i++) {
        uint32_t packed[2];
        int8_t* pb = reinterpret_cast<int8_t*>(packed);
        #pragma unroll
        for (int j = 0; j < 8; j++) {
            int q = __float2int_rn(__fdiv_rn(vals[i * 8 + j], scale));
            q = max(-127, min(127, q));
            pb[j] = (int8_t)q;
        }
        reinterpret_cast<uint2*>(qr)[i * 256 + tid] = make_uint2(packed[0], packed[1]);
    }
}

// ---------------------------------------------------------------------------
// Kernel 1b: out[m][n] = bias[n]. Pure streaming write now.
// ---------------------------------------------------------------------------
__global__ void __launch_bounds__(256) bias_init_kernel(
    const void* __restrict__ p_bias, float* __restrict__ out, int N, int total4)
{
    int idx = blockIdx.x * 256 + threadIdx.x;
    if (idx >= total4) return;
    const int bmode = g_bmode;
    int n = (idx * 4) % N;
    float4 b;
    if (bmode == 0) {
        b = *(const float4*)((const float*)p_bias + n);
    } else if (bmode == 1) {
        const __half* bh = (const __half*)p_bias + n;
        b = make_float4(__half2float(bh[0]), __half2float(bh[1]),
                        __half2float(bh[2]), __half2float(bh[3]));
    } else {
        const uint16_t* bb = (const uint16_t*)p_bias + n;
        b = make_float4(__uint_as_float((uint32_t)bb[0] << 16),
                        __uint_as_float((uint32_t)bb[1] << 16),
                        __uint_as_float((uint32_t)bb[2] << 16),
                        __uint_as_float((uint32_t)bb[3] << 16));
    }
    *(float4*)(out + (size_t)idx * 4) = b;
}

// ---------------------------------------------------------------------------
// Kernel 2: persistent K-split int8 GEMM, ldmatrix fragment loads.
// 296 CTAs; unit u -> tile u/64 (bn = tile>>1, bm = tile&1), kt = u%64.
// Partials combined via atomicAdd into bias-initialized out.
// ---------------------------------------------------------------------------
template <bool WI32>
__global__ void __launch_bounds__(THREADS, 2) gemm_kernel(
    const void* __restrict__ Wv,
    const float* __restrict__ scale_channel,
    float* __restrict__ out,
    int N, int K)
{
    if (g_wi32 != (WI32 ? 1 : 0)) return;

    extern __shared__ char smem[];
    const int tid  = threadIdx.x;
    const int warp = tid >> 5;
    const int lane = tid & 31;
    const int wm   = warp & 3;          // 4 warps along M
    const int wn   = warp >> 2;         // 2 warps along N

    // ldmatrix lane address components
    const int aR = (lane & 7) + ((lane >> 3) & 1) * 8;  // A: row within m16
    const int aC = ((lane >> 4) & 1) * 16;              // A: k-half byte offset
    const int bM = lane >> 3;                           // B x4: matrix id
    const int bR = lane & 7;

    const int*    gB32 = (const int*)Wv;
    const int8_t* gB8  = (const int8_t*)Wv;

    const int NK     = K / BK;                    // 64
    const int tilesN = N / BN;                    // 256
    const int totalU = tilesN * 2 * NK;           // 32768
    const int per    = totalU / GRID;
    const int rem    = totalU % GRID;
    const int cta    = blockIdx.x;
    int u = cta * per + min(cta, rem);
    const int uend = u + per + (cta < rem ? 1 : 0);

    float* s_scale = (float*)(smem);

    while (u < uend) {
        const int tile = u / NK;
        const int kt0  = u - tile * NK;
        const int kcnt = min(NK - kt0, uend - u);
        const int bn   = tile >> 1;
        const int bm   = tile & 1;
        const int8_t* gA = g_qx + (size_t)(bm * BM) * K;

        int acc[2][7][4];
        #pragma unroll
        for (int i = 0; i < 2; i++)
            #pragma unroll
            for (int j = 0; j < 7; j++)
                #pragma unroll
                for (int l = 0; l < 4; l++) acc[i][j][l] = 0;

        uint32_t rw[14];
        auto ldgW = [&](int j) {
            if (!WI32) return;
            const int k0 = (kt0 + j) * BK;
            #pragma unroll
            for (int i = 0; i < 14; i++) {
                int c   = tid + i * THREADS;
                int row = c >> 5;
                int ch  = c & 31;
                const int* src = gB32 + (size_t)(bn * BN + row) * K + k0 + ch * 4;
                rw[i] = pack4(*(const uint4*)src);
            }
        };
        auto stsW = [&](int st) {
            if (!WI32) return;
            char* wBase = smem + SM_HDR + st * SM_STAGE + A_BYTES;
            #pragma unroll
            for (int i = 0; i < 14; i++) {
                int c   = tid + i * THREADS;
                int row = c >> 5;
                int ch  = c & 31;
                *(uint32_t*)(wBase + row * W_STRIDE + ch * 4) = rw[i];
            }
        };
        auto cpA = [&](int j, int st) {
            char* aBase = smem + SM_HDR + st * SM_STAGE;
            const int k0 = (kt0 + j) * BK;
            #pragma unroll
            for (int i = 0; i < 4; i++) {
                int task = tid + i * THREADS;
                int row  = task >> 3;
                int ch   = (task & 7) * 16;
                uint32_t dst = smem_u32(aBase + row * A_STRIDE + ch);
                const int8_t* src = gA + (size_t)row * K + k0 + ch;
                asm volatile("cp.async.cg.shared.global [%0], [%1], 16;\n"
                             :: "r"(dst), "l"(src));
            }
            if (!WI32) {
                char* wBase = aBase + A_BYTES;
                for (int task = tid; task < BN * 8; task += THREADS) {
                    int row = task >> 3;
                    int ch  = (task & 7) * 16;
                    uint32_t dst = smem_u32(wBase + row * W_STRIDE + ch);
                    const int8_t* src = gB8 + (size_t)(bn * BN + row) * K + k0 + ch;
                    asm volatile("cp.async.cg.shared.global [%0], [%1], 16;\n"
                                 :: "r"(dst), "l"(src));
                }
            }
            asm volatile("cp.async.commit_group;\n");
        };

        // prologue
        ldgW(0);
        cpA(0, 0);
        if (kcnt > 1) cpA(1, 1);
        stsW(0);
        if (kcnt > 1) ldgW(1);

        for (int j = 0; j < kcnt; j++) {
            if (j + 1 < kcnt) asm volatile("cp.async.wait_group 1;\n");
            else              asm volatile("cp.async.wait_group 0;\n");
            __syncthreads();

            const uint32_t sAu = smem_u32(smem + SM_HDR + (j & 1) * SM_STAGE);
            const uint32_t sWu = sAu + A_BYTES;

            #pragma unroll
            for (int kc = 0; kc < 4; kc++) {
                const int kofs = kc * 32;
                // A fragments: 2 ldmatrix.x4
                uint32_t a[2][4];
                #pragma unroll
                for (int mt = 0; mt < 2; mt++)
                    ldsm4(a[mt], sAu + (wm * 32 + mt * 16 + aR) * A_STRIDE + kofs + aC);
                // B fragments: 3 x4 + 1 x2 covering 7 nt
                uint32_t b[7][2];
                #pragma unroll
                for (int p = 0; p < 3; p++) {
                    uint32_t r4[4];
                    ldsm4(r4, sWu + (wn * 56 + (2 * p + (bM >> 1)) * 8 + bR) * W_STRIDE
                              + kofs + (bM & 1) * 16);
                    b[2 * p][0]     = r4[0];
                    b[2 * p][1]     = r4[1];
                    b[2 * p + 1][0] = r4[2];
                    b[2 * p + 1][1] = r4[3];
                }
                {
                    uint32_t r2[2];
                    ldsm2(r2, sWu + (wn * 56 + 48 + bR) * W_STRIDE
                              + kofs + ((lane >> 3) & 1) * 16);
                    b[6][0] = r2[0];
                    b[6][1] = r2[1];
                }
                #pragma unroll
                for (int nt = 0; nt < 7; nt++)
                    #pragma unroll
                    for (int mt = 0; mt < 2; mt++) {
                        asm volatile(
                            "mma.sync.aligned.m16n8k32.row.col.s32.s8.s8.s32 "
                            "{%0,%1,%2,%3}, {%4,%5,%6,%7}, {%8,%9}, {%0,%1,%2,%3};\n"
                            : "+r"(acc[mt][nt][0]), "+r"(acc[mt][nt][1]),
                              "+r"(acc[mt][nt][2]), "+r"(acc[mt][nt][3])
                            : "r"(a[mt][0]), "r"(a[mt][1]), "r"(a[mt][2]), "r"(a[mt][3]),
                              "r"(b[nt][0]), "r"(b[nt][1]));
                    }
            }

            __syncthreads();
            if (j + 2 < kcnt) cpA(j + 2, j & 1);
            if (j + 1 < kcnt) stsW((j + 1) & 1);
            if (j + 2 < kcnt) ldgW(j + 2);
        }

        // ---- atomic dequant epilogue ----
        if (tid < BN) s_scale[tid] = scale_channel[bn * BN + tid];
        __syncthreads();

        #pragma unroll
        for (int mt = 0; mt < 2; mt++) {
            int row0 = bm * BM + wm * 32 + mt * 16 + (lane >> 2);
            float s0 = g_ascale[row0];
            float s1 = g_ascale[row0 + 8];
            #pragma unroll
            for (int nt = 0; nt < 7; nt++) {
                int lc = wn * 56 + nt * 8 + (lane & 3) * 2;
                float sc0 = s_scale[lc], sc1 = s_scale[lc + 1];
                int gcol = bn * BN + lc;
                float* o0 = out + (size_t)row0 * N + gcol;
                float* o1 = out + (size_t)(row0 + 8) * N + gcol;
                atomicAdd(o0,     (float)acc[mt][nt][0] * s0 * sc0);
                atomicAdd(o0 + 1, (float)acc[mt][nt][1] * s0 * sc1);
                atomicAdd(o1,     (float)acc[mt][nt][2] * s1 * sc0);
                atomicAdd(o1 + 1, (float)acc[mt][nt][3] * s1 * sc1);
            }
        }
        __syncthreads();

        u += kcnt;
    }
}

// ---------------------------------------------------------------------------
extern "C" void kernel_launch(void* const* d_in, const int* in_sizes, int n_in,
                              void* d_out, int out_size) {
    const void*  x    = d_in[0];
    const void*  w    = d_in[1];
    const float* sc   = (const float*)d_in[2];
    const void*  bias = d_in[3];
    float* out = (float*)d_out;

    const int N = in_sizes[2];            // 28672
    const int K = in_sizes[1] / N;        // 8192
    const int M = in_sizes[0] / K;        // 256

    detect_kernel<<<1, 32>>>(x, bias, w);

    quant_kernel<0><<<M, 256>>>(x, K);
    quant_kernel<1><<<M, 256>>>(x, K);
    quant_kernel<2><<<M, 256>>>(x, K);

    const int total4 = M * N / 4;
    bias_init_kernel<<<(total4 + 255) / 256, 256>>>(bias, out, N, total4);

    cudaFuncSetAttribute(gemm_kernel<true >, cudaFuncAttributeMaxDynamicSharedMemorySize, SM_TOTAL);
    cudaFuncSetAttribute(gemm_kernel<false>, cudaFuncAttributeMaxDynamicSharedMemorySize, SM_TOTAL);

    gemm_kernel<true ><<<GRID, THREADS, SM_TOTAL>>>(w, sc, out, N, K);
    gemm_kernel<false><<<GRID, THREADS, SM_TOTAL>>>(w, sc, out, N, K);
}